// round 14
// baseline (speedup 1.0000x reference)
#include <cuda_runtime.h>

#define S_   4
#define B_   8
#define L_   512
#define D_   128
#define NOP_ 64
#define W_   2048   // S_*L_
#define NBLK_ 148
#define MAXG_ 10    // covers N up to 5920 selected words (dataset N ~2950)

// smem float offsets for k_update
#define OFF_WW   0
#define OFF_UW   16384
#define OFF_AS   32768
#define OFF_HS   33296
#define OFF_USM  33824
#define OFF_CFV  39104
#define OFF_SSP  39108
#define OFF_GL   39140
#define SMEM_UPD_FLOATS 39180   // 156720 bytes

// ---------------- scratch (device globals; no allocation) ----------------
__device__ float g_agg[B_ * W_ * 3 * D_];   // per selected word: [a_o | a_k(normed) | a_s(normed)]
__device__ float g_coef[B_ * W_ * 4];       // [cO, rowsumK, rowsumS]
__device__ float g_goal[B_ * D_];           // pooled sum of relu(word_updated)
__device__ int   g_bcnt[B_];
__device__ int   g_list[B_ * W_];
__device__ int   g_n;
__device__ int   g_done;

// ---------------- helpers ----------------
__device__ __forceinline__ void add4(float4& a, const float4 v) {
    a.x += v.x; a.y += v.y; a.z += v.z; a.w += v.w;
}

// ---------------- kernel 0: reset ----------------
__global__ void k_reset() {
    int t = threadIdx.x;
    if (t < B_ * D_) g_goal[t] = 0.f;
    if (t < B_) g_bcnt[t] = 0;
    if (t == 0) { g_n = 0; g_done = 0; }
}

// ---------------- kernel 1: aggregate neighbors (proven form, unchanged) ----------------
__global__ void __launch_bounds__(128) k_aggregate(
    const float* __restrict__ word_outputs,
    const float* __restrict__ op_embedding,
    const float* __restrict__ word_operator,
    const float* __restrict__ word_word,
    const float* __restrict__ depend_relation,
    const float* __restrict__ word_exist_matrix,
    const float* __restrict__ word_exist_seq,
    const float* __restrict__ goal_word)
{
    const int w = blockIdx.x, b = blockIdx.y;
    const int bw = b * W_ + w;
    if (goal_word[bw] == 0.f || word_exist_seq[bw] == 0.f) return;

    const int tid = threadIdx.x;
    const int lane = tid & 31, wid = tid >> 5;
    const unsigned lt = (1u << lane) - 1u;

    __shared__ int   listK[4][512];
    __shared__ int   listS[4][128];
    __shared__ int   listO[64];
    __shared__ float comb[4][3][128];
    __shared__ int   scn[4][2];

    float4 accO = {0,0,0,0}, accK = {0,0,0,0}, accS = {0,0,0,0};
    int cK = 0, cS = 0, cOv = 0;

    // ---- operator part: gather raw op_embedding rows, warp 0 only ----
    if (wid == 0) {
        const float4* wo4 = (const float4*)(word_operator + (size_t)bw * NOP_);
        float4 m = (lane < 16) ? wo4[lane] : make_float4(0.f,0.f,0.f,0.f);
        int col0 = lane * 4, cO = 0;
        unsigned bb;
        bb = __ballot_sync(0xffffffffu, m.x != 0.f); if (m.x != 0.f) listO[cO + __popc(bb & lt)] = col0;     cO += __popc(bb);
        bb = __ballot_sync(0xffffffffu, m.y != 0.f); if (m.y != 0.f) listO[cO + __popc(bb & lt)] = col0 + 1; cO += __popc(bb);
        bb = __ballot_sync(0xffffffffu, m.z != 0.f); if (m.z != 0.f) listO[cO + __popc(bb & lt)] = col0 + 2; cO += __popc(bb);
        bb = __ballot_sync(0xffffffffu, m.w != 0.f); if (m.w != 0.f) listO[cO + __popc(bb & lt)] = col0 + 3; cO += __popc(bb);
        __syncwarp();
        const float* pb = op_embedding + (size_t)b * NOP_ * D_;
        float4 o0 = {0,0,0,0}, o1 = {0,0,0,0};
        int i = 0;
        for (; i + 2 <= cO; i += 2) {
            float4 v0 = ((const float4*)(pb + (size_t)listO[i]     * D_))[lane];
            float4 v1 = ((const float4*)(pb + (size_t)listO[i + 1] * D_))[lane];
            add4(o0, v0); add4(o1, v1);
        }
        if (i < cO) add4(o0, ((const float4*)(pb + (size_t)listO[i] * D_))[lane]);
        accO = o0; add4(accO, o1);
        cOv = cO;
    }

    // ---- knowledge part ----
    {
        const float4* ww4 = (const float4*)(word_word + (size_t)bw * W_);
        const float4* we4 = (const float4*)(word_exist_matrix + (size_t)bw * W_);
        const int cbase = wid * 512;
        #pragma unroll
        for (int c4 = 0; c4 < 4; ++c4) {
            int vec = wid * 128 + c4 * 32 + lane;
            float4 m1 = ww4[vec], m2 = we4[vec];
            float mx = m1.x * m2.x, my = m1.y * m2.y, mz = m1.z * m2.z, mw = m1.w * m2.w;
            int col0 = cbase + c4 * 128 + lane * 4;
            unsigned bb;
            bb = __ballot_sync(0xffffffffu, mx != 0.f); if (mx != 0.f) listK[wid][cK + __popc(bb & lt)] = col0;     cK += __popc(bb);
            bb = __ballot_sync(0xffffffffu, my != 0.f); if (my != 0.f) listK[wid][cK + __popc(bb & lt)] = col0 + 1; cK += __popc(bb);
            bb = __ballot_sync(0xffffffffu, mz != 0.f); if (mz != 0.f) listK[wid][cK + __popc(bb & lt)] = col0 + 2; cK += __popc(bb);
            bb = __ballot_sync(0xffffffffu, mw != 0.f); if (mw != 0.f) listK[wid][cK + __popc(bb & lt)] = col0 + 3; cK += __popc(bb);
        }
        __syncwarp();
        float4 k0 = {0,0,0,0}, k1 = {0,0,0,0}, k2 = {0,0,0,0}, k3 = {0,0,0,0};
        int i = 0;
        for (; i + 4 <= cK; i += 4) {
            int j0 = listK[wid][i], j1 = listK[wid][i+1], j2 = listK[wid][i+2], j3 = listK[wid][i+3];
            float4 v0 = ((const float4*)(word_outputs + (((size_t)(j0 >> 9) * B_ + b) * L_ + (j0 & 511)) * D_))[lane];
            float4 v1 = ((const float4*)(word_outputs + (((size_t)(j1 >> 9) * B_ + b) * L_ + (j1 & 511)) * D_))[lane];
            float4 v2 = ((const float4*)(word_outputs + (((size_t)(j2 >> 9) * B_ + b) * L_ + (j2 & 511)) * D_))[lane];
            float4 v3 = ((const float4*)(word_outputs + (((size_t)(j3 >> 9) * B_ + b) * L_ + (j3 & 511)) * D_))[lane];
            add4(k0, v0); add4(k1, v1); add4(k2, v2); add4(k3, v3);
        }
        for (; i < cK; ++i) {
            int j0 = listK[wid][i];
            add4(k0, ((const float4*)(word_outputs + (((size_t)(j0 >> 9) * B_ + b) * L_ + (j0 & 511)) * D_))[lane]);
        }
        add4(k0, k1); add4(k2, k3); accK = k0; add4(accK, k2);
    }

    // ---- segment dependency part ----
    {
        const int s = w >> 9, l = w & 511;
        const float4* dp4 = (const float4*)(depend_relation + (((size_t)s * B_ + b) * L_ + l) * L_);
        const float* xb = word_outputs + ((size_t)s * B_ + b) * L_ * D_;
        float4 m = dp4[wid * 32 + lane];
        int col0 = wid * 128 + lane * 4;
        unsigned bb;
        bb = __ballot_sync(0xffffffffu, m.x != 0.f); if (m.x != 0.f) listS[wid][cS + __popc(bb & lt)] = col0;     cS += __popc(bb);
        bb = __ballot_sync(0xffffffffu, m.y != 0.f); if (m.y != 0.f) listS[wid][cS + __popc(bb & lt)] = col0 + 1; cS += __popc(bb);
        bb = __ballot_sync(0xffffffffu, m.z != 0.f); if (m.z != 0.f) listS[wid][cS + __popc(bb & lt)] = col0 + 2; cS += __popc(bb);
        bb = __ballot_sync(0xffffffffu, m.w != 0.f); if (m.w != 0.f) listS[wid][cS + __popc(bb & lt)] = col0 + 3; cS += __popc(bb);
        __syncwarp();
        float4 s0 = {0,0,0,0}, s1 = {0,0,0,0}, s2 = {0,0,0,0}, s3 = {0,0,0,0};
        int i = 0;
        for (; i + 4 <= cS; i += 4) {
            int j0 = listS[wid][i], j1 = listS[wid][i+1], j2 = listS[wid][i+2], j3 = listS[wid][i+3];
            float4 v0 = ((const float4*)(xb + (size_t)j0 * D_))[lane];
            float4 v1 = ((const float4*)(xb + (size_t)j1 * D_))[lane];
            float4 v2 = ((const float4*)(xb + (size_t)j2 * D_))[lane];
            float4 v3 = ((const float4*)(xb + (size_t)j3 * D_))[lane];
            add4(s0, v0); add4(s1, v1); add4(s2, v2); add4(s3, v3);
        }
        for (; i < cS; ++i)
            add4(s0, ((const float4*)(xb + (size_t)listS[wid][i] * D_))[lane]);
        add4(s0, s1); add4(s2, s3); accS = s0; add4(accS, s2);
    }

    // ---- cross-warp combine ----
    *(float4*)&comb[wid][0][4 * lane] = accO;
    *(float4*)&comb[wid][1][4 * lane] = accK;
    *(float4*)&comb[wid][2][4 * lane] = accS;
    if (lane == 0) { scn[wid][0] = cK; scn[wid][1] = cS; }
    __syncthreads();

    const int d = tid;
    float aO = comb[0][0][d] + comb[1][0][d] + comb[2][0][d] + comb[3][0][d];
    float aK = comb[0][1][d] + comb[1][1][d] + comb[2][1][d] + comb[3][1][d];
    float aS = comb[0][2][d] + comb[1][2][d] + comb[2][2][d] + comb[3][2][d];
    int tK = scn[0][0] + scn[1][0] + scn[2][0] + scn[3][0];
    int tS = scn[0][1] + scn[1][1] + scn[2][1] + scn[3][1];
    float invK = 1.f / ((float)tK + 1e-30f);
    float invS = 1.f / ((float)tS + 1e-30f);

    float* ag = g_agg + (size_t)bw * 384;
    ag[d]       = aO;
    ag[128 + d] = aK * invK;
    ag[256 + d] = aS * invS;
    if (tid == 0) {
        g_coef[bw * 4 + 0] = (float)cOv;
        g_coef[bw * 4 + 1] = (float)tK * invK;
        g_coef[bw * 4 + 2] = (float)tS * invS;
        int pos = atomicAdd(&g_n, 1);
        g_list[pos] = bw;
        atomicAdd(&g_bcnt[b], 1);
    }
}

// ---------------- kernel 2: block-cooperative update + fused finale ----------------
// 148 blocks x 256 threads. Block processes groups of 4 words; warp wp owns
// dims [16wp,16wp+16); lane owns word (lane>>3) x 2 dims. Weights for the
// current part (Wp 64KB + Up_p 64KB) staged in smem, shared by all 8 warps.
// After a resident-grid barrier, blocks 0..7 compute the gate finale.
__global__ void __launch_bounds__(256) k_update(
    const float* __restrict__ o_w_W, const float* __restrict__ o_w_b,
    const float* __restrict__ wk_W,  const float* __restrict__ wk_b,
    const float* __restrict__ ws_W,  const float* __restrict__ ws_b,
    const float* __restrict__ up_W,  const float* __restrict__ up_b,
    const float* __restrict__ node_hidden,
    const float* __restrict__ wg_W, const float* __restrict__ wg_b,
    const float* __restrict__ fg_W, const float* __restrict__ fg_b,
    float* __restrict__ out)
{
    extern __shared__ float sm[];
    float* wW  = sm + OFF_WW;    // 16384: current part feature weights
    float* uWs = sm + OFF_UW;    // 16384: current part up-proj slice
    float* as_ = sm + OFF_AS;    // 4 x 132 padded
    float* hs  = sm + OFF_HS;    // 4 x 132 padded
    float* usm = sm + OFF_USM;   // MAXG_ x 528: u partials
    float* cfv = sm + OFF_CFV;   // 4
    float* ssp = sm + OFF_SSP;   // 4 words x 8 warps
    int*   gl  = (int*)(sm + OFF_GL);  // MAXG_ x 4

    const int tid = threadIdx.x;
    const int wp = tid >> 5, lane = tid & 31;
    const int wsel = lane >> 3;
    const int dim0 = wp * 16 + (lane & 7) * 2;
    const int N = g_n;

    if (tid < MAXG_ * 4) {
        int gi = tid >> 2, ww = tid & 3;
        int word = (gi * (int)gridDim.x + (int)blockIdx.x) * 4 + ww;
        gl[tid] = (word < N) ? g_list[word] : -1;
    }

    #pragma unroll 1
    for (int p = 0; p < 3; ++p) {
        __syncthreads();   // previous part's smem reads complete
        const float* Wg = (p == 0) ? o_w_W : (p == 1) ? wk_W : ws_W;
        const float* Ug = up_W + p * 16384;
        #pragma unroll
        for (int i = 0; i < 16; ++i) {
            int off = i * 256 + tid;
            ((float4*)wW)[off]  = ((const float4*)Wg)[off];
            ((float4*)uWs)[off] = ((const float4*)Ug)[off];
        }
        const float* bp = (p == 0) ? o_w_b : (p == 1) ? wk_b : ws_b;
        const float2 bia = *(const float2*)(bp + dim0);

        #pragma unroll 1
        for (int gi = 0; gi < MAXG_; ++gi) {
            int base = (gi * (int)gridDim.x + (int)blockIdx.x) * 4;
            if (base >= N) break;
            // stage aggregates + coefs for this group/part
            {
                int ww = tid >> 6, j = tid & 63;
                int wd = gl[gi * 4 + ww];
                float2 v = make_float2(0.f, 0.f);
                if (wd >= 0) v = *(const float2*)(g_agg + (size_t)wd * 384 + p * 128 + j * 2);
                *(float2*)(&as_[ww * 132 + j * 2]) = v;
                if (tid < 4) {
                    int wd2 = gl[gi * 4 + tid];
                    cfv[tid] = (wd2 >= 0) ? g_coef[wd2 * 4 + p] : 0.f;
                }
            }
            __syncthreads();   // as_/cfv staged (also weights on first gi)

            // feature GEMV for (word wsel, dims dim0..dim0+1)
            float cf = cfv[wsel];
            float2 h = make_float2(cf * bia.x, cf * bia.y);
            #pragma unroll 8
            for (int k4 = 0; k4 < 32; ++k4) {
                float4 a4 = *(const float4*)(&as_[wsel * 132 + k4 * 4]);
                float2 w0 = *(const float2*)(&wW[(k4 * 4 + 0) * 128 + dim0]);
                float2 w1 = *(const float2*)(&wW[(k4 * 4 + 1) * 128 + dim0]);
                float2 w2 = *(const float2*)(&wW[(k4 * 4 + 2) * 128 + dim0]);
                float2 w3 = *(const float2*)(&wW[(k4 * 4 + 3) * 128 + dim0]);
                h.x = fmaf(a4.x, w0.x, fmaf(a4.y, w1.x, fmaf(a4.z, w2.x, fmaf(a4.w, w3.x, h.x))));
                h.y = fmaf(a4.x, w0.y, fmaf(a4.y, w1.y, fmaf(a4.z, w2.y, fmaf(a4.w, w3.y, h.y))));
            }
            // L2 norm: 8-lane group partial -> cross-warp via smem
            float ss = h.x * h.x + h.y * h.y;
            ss += __shfl_xor_sync(0xffffffffu, ss, 1);
            ss += __shfl_xor_sync(0xffffffffu, ss, 2);
            ss += __shfl_xor_sync(0xffffffffu, ss, 4);
            if ((lane & 7) == 0) ssp[wsel * 8 + wp] = ss;
            __syncthreads();
            float tot = ssp[wsel*8+0] + ssp[wsel*8+1] + ssp[wsel*8+2] + ssp[wsel*8+3]
                      + ssp[wsel*8+4] + ssp[wsel*8+5] + ssp[wsel*8+6] + ssp[wsel*8+7];
            float inv = 1.f / (sqrtf(tot) + 1e-30f);
            *(float2*)(&hs[wsel * 132 + dim0]) = make_float2(h.x * inv, h.y * inv);
            __syncthreads();
            // up-projection for this part
            float2 du = make_float2(0.f, 0.f);
            #pragma unroll 8
            for (int k4 = 0; k4 < 32; ++k4) {
                float4 h4 = *(const float4*)(&hs[wsel * 132 + k4 * 4]);
                float2 w0 = *(const float2*)(&uWs[(k4 * 4 + 0) * 128 + dim0]);
                float2 w1 = *(const float2*)(&uWs[(k4 * 4 + 1) * 128 + dim0]);
                float2 w2 = *(const float2*)(&uWs[(k4 * 4 + 2) * 128 + dim0]);
                float2 w3 = *(const float2*)(&uWs[(k4 * 4 + 3) * 128 + dim0]);
                du.x = fmaf(h4.x, w0.x, fmaf(h4.y, w1.x, fmaf(h4.z, w2.x, fmaf(h4.w, w3.x, du.x))));
                du.y = fmaf(h4.x, w0.y, fmaf(h4.y, w1.y, fmaf(h4.z, w2.y, fmaf(h4.w, w3.y, du.y))));
            }
            float* up = &usm[gi * 528 + wsel * 132 + dim0];
            if (p == 0) { up[0] = du.x;  up[1] = du.y;  }
            else        { up[0] += du.x; up[1] += du.y; }
            __syncthreads();   // protect as_/hs reuse by next group
        }
    }
    __syncthreads();

    // relu + pooled accumulation (bias added here; usm written by this thread)
    {
        const float2 ub = *(const float2*)(up_b + dim0);
        for (int gi = 0; gi < MAXG_; ++gi) {
            int base = (gi * (int)gridDim.x + (int)blockIdx.x) * 4;
            if (base >= N) break;
            int wd = gl[gi * 4 + wsel];
            if (wd >= 0) {
                const float* up = &usm[gi * 528 + wsel * 132 + dim0];
                int b = wd >> 11;
                atomicAdd(&g_goal[b * 128 + dim0],     fmaxf(up[0] + ub.x, 0.f));
                atomicAdd(&g_goal[b * 128 + dim0 + 1], fmaxf(up[1] + ub.y, 0.f));
            }
        }
    }

    // ---- resident-grid barrier ----
    __syncthreads();
    if (tid == 0) {
        __threadfence();
        atomicAdd(&g_done, 1);
    }
    if (blockIdx.x >= B_) return;
    if (tid == 0) {
        while (atomicAdd(&g_done, 0) < (int)gridDim.x) { }
    }
    __syncthreads();

    // ---- finale for batch b = blockIdx.x (smem aliases wW, done being used) ----
    {
        const int b = blockIdx.x;
        const int d = tid & 127, kh = tid >> 7;
        float* gws = sm;
        float* nh  = sm + 128;
        float* pp1 = sm + 256;
        float* pp2 = sm + 512;
        if (tid < 128) {
            float invc = 1.f / ((float)g_bcnt[b] + 1e-30f);
            gws[tid] = __ldcg(&g_goal[b * 128 + tid]) * invc;
            nh[tid]  = node_hidden[b * 128 + tid];
        }
        __syncthreads();

        float s1 = 0.f, s2 = 0.f;
        #pragma unroll 4
        for (int i = 0; i < 64; ++i) {
            int k = kh * 64 + i;
            s1 = fmaf(gws[k], wg_W[k * 128 + d], s1);
        }
        #pragma unroll 4
        for (int i = 0; i < 128; ++i) {
            int k = kh * 128 + i;
            float x = (k < 128) ? gws[k] : nh[k - 128];
            s2 = fmaf(x, fg_W[k * 128 + d], s2);
        }
        pp1[kh * 128 + d] = s1;
        pp2[kh * 128 + d] = s2;
        __syncthreads();

        if (tid < 128) {
            float t1 = pp1[tid] + pp1[128 + tid] + wg_b[tid];
            float t2 = pp2[tid] + pp2[128 + tid] + fg_b[tid];
            float gu = fmaxf(t1, 0.f);
            float f  = 1.f / (1.f + expf(-t2));
            out[b * 128 + tid] = fmaxf(f, 0.1f) * nh[tid] + (1.f - f) * gu;
        }
    }
}

// ---------------- launch ----------------
extern "C" void kernel_launch(void* const* d_in, const int* in_sizes, int n_in,
                              void* d_out, int out_size) {
    const float* word_outputs      = (const float*)d_in[0];
    const float* node_hidden       = (const float*)d_in[1];
    const float* op_embedding      = (const float*)d_in[2];
    const float* word_operator     = (const float*)d_in[3];
    const float* word_word         = (const float*)d_in[4];
    const float* depend_relation   = (const float*)d_in[5];
    const float* word_exist_matrix = (const float*)d_in[6];
    const float* word_exist_seq    = (const float*)d_in[7];
    const float* goal_word         = (const float*)d_in[8];
    const float* o_w_W = (const float*)d_in[9];
    const float* o_w_b = (const float*)d_in[10];
    const float* wk_W  = (const float*)d_in[11];
    const float* wk_b  = (const float*)d_in[12];
    const float* ws_W  = (const float*)d_in[13];
    const float* ws_b  = (const float*)d_in[14];
    const float* up_W  = (const float*)d_in[15];
    const float* up_b  = (const float*)d_in[16];
    const float* wg_W  = (const float*)d_in[17];
    const float* wg_b  = (const float*)d_in[18];
    const float* fg_W  = (const float*)d_in[19];
    const float* fg_b  = (const float*)d_in[20];
    float* out = (float*)d_out;

    static bool attr_set = false;
    if (!attr_set) {
        cudaFuncSetAttribute(k_update, cudaFuncAttributeMaxDynamicSharedMemorySize,
                             SMEM_UPD_FLOATS * 4);
        attr_set = true;
    }

    k_reset<<<1, 1024>>>();
    k_aggregate<<<dim3(W_, B_), 128>>>(word_outputs, op_embedding, word_operator,
                                       word_word, depend_relation, word_exist_matrix,
                                       word_exist_seq, goal_word);
    k_update<<<NBLK_, 256, SMEM_UPD_FLOATS * 4>>>(
        o_w_W, o_w_b, wk_W, wk_b, ws_W, ws_b, up_W, up_b,
        node_hidden, wg_W, wg_b, fg_W, fg_b, out);
}

// round 15
// speedup vs baseline: 1.0303x; 1.0303x over previous
#include <cuda_runtime.h>

#define S_   4
#define B_   8
#define L_   512
#define D_   128
#define NOP_ 64
#define W_   2048   // S_*L_

// ---------------- scratch (device globals; no allocation) ----------------
__device__ float g_agg[B_ * W_ * 3 * D_];   // per selected word: [h_o | a_k(normed) | a_s(normed)]
__device__ float g_coef[B_ * W_ * 4];       // [cO, rowsumK, rowsumS]
__device__ float g_opproj[B_ * NOP_ * D_];  // op_embedding @ o_w_W + o_w_b
__device__ float g_goal[B_ * D_];           // pooled sum of relu(word_updated)
__device__ int   g_bcnt[B_];
__device__ int   g_list[B_ * W_];
__device__ int   g_n;

// ---------------- helpers ----------------
__device__ __forceinline__ void add4(float4& a, const float4 v) {
    a.x += v.x; a.y += v.y; a.z += v.z; a.w += v.w;
}

// ---------------- kernel 1: prep = reset + op projection (efficient) ----------------
// grid 64 x 256. Block bi computes 8 rows of proj[b,o,:] = emb@W + b.
// Thread owns 4 output cols of one row; emb rows staged in smem, weight
// reads coalesced LDG.128. Block 0 also resets counters/accumulators.
__global__ void __launch_bounds__(256) k_prep(
    const float* __restrict__ op_embedding,
    const float* __restrict__ o_w_W, const float* __restrict__ o_w_b)
{
    const int tid = threadIdx.x;
    if (blockIdx.x == 0) {
        for (int t = tid; t < B_ * D_; t += 256) g_goal[t] = 0.f;
        if (tid < B_) g_bcnt[tid] = 0;
        if (tid == 0) g_n = 0;
    }

    const int r = tid >> 5;            // 0..7 (row within block)
    const int c4 = (tid & 31) * 4;     // output col block
    const int row = blockIdx.x * 8 + r;   // 0..511 = b*64 + o
    __shared__ float es[8][128];

    *(float4*)&es[r][c4] = *(const float4*)(op_embedding + (size_t)row * D_ + c4);
    __syncthreads();

    float4 acc = *(const float4*)(o_w_b + c4);
    #pragma unroll 4
    for (int dd = 0; dd < 128; ++dd) {
        float e = es[r][dd];
        float4 w = *(const float4*)(o_w_W + dd * 128 + c4);
        acc.x = fmaf(e, w.x, acc.x); acc.y = fmaf(e, w.y, acc.y);
        acc.z = fmaf(e, w.z, acc.z); acc.w = fmaf(e, w.w, acc.w);
    }
    *(float4*)(g_opproj + (size_t)row * D_ + c4) = acc;
}

// ---------------- kernel 2: aggregate neighbors (proven R3 form) ----------------
// Operator part gathers PRE-PROJECTED rows from g_opproj (H-space, bias incl).
__global__ void __launch_bounds__(128) k_aggregate(
    const float* __restrict__ word_outputs,
    const float* __restrict__ word_operator,
    const float* __restrict__ word_word,
    const float* __restrict__ depend_relation,
    const float* __restrict__ word_exist_matrix,
    const float* __restrict__ word_exist_seq,
    const float* __restrict__ goal_word)
{
    const int w = blockIdx.x, b = blockIdx.y;
    const int bw = b * W_ + w;
    if (goal_word[bw] == 0.f || word_exist_seq[bw] == 0.f) return;

    const int tid = threadIdx.x;
    const int lane = tid & 31, wid = tid >> 5;
    const unsigned lt = (1u << lane) - 1u;

    __shared__ int   listK[4][512];
    __shared__ int   listS[4][128];
    __shared__ int   listO[64];
    __shared__ float comb[4][3][128];
    __shared__ int   scn[4][2];

    float4 accO = {0,0,0,0}, accK = {0,0,0,0}, accS = {0,0,0,0};
    int cK = 0, cS = 0;

    // ---- operator part: gather projected rows (H-space), warp 0 only ----
    if (wid == 0) {
        const float4* wo4 = (const float4*)(word_operator + (size_t)bw * NOP_);
        float4 m = (lane < 16) ? wo4[lane] : make_float4(0.f,0.f,0.f,0.f);
        int col0 = lane * 4, cO = 0;
        unsigned bb;
        bb = __ballot_sync(0xffffffffu, m.x != 0.f); if (m.x != 0.f) listO[cO + __popc(bb & lt)] = col0;     cO += __popc(bb);
        bb = __ballot_sync(0xffffffffu, m.y != 0.f); if (m.y != 0.f) listO[cO + __popc(bb & lt)] = col0 + 1; cO += __popc(bb);
        bb = __ballot_sync(0xffffffffu, m.z != 0.f); if (m.z != 0.f) listO[cO + __popc(bb & lt)] = col0 + 2; cO += __popc(bb);
        bb = __ballot_sync(0xffffffffu, m.w != 0.f); if (m.w != 0.f) listO[cO + __popc(bb & lt)] = col0 + 3; cO += __popc(bb);
        __syncwarp();
        const float* pb = g_opproj + (size_t)b * NOP_ * D_;
        float4 o0 = {0,0,0,0}, o1 = {0,0,0,0};
        int i = 0;
        for (; i + 2 <= cO; i += 2) {
            float4 v0 = ((const float4*)(pb + (size_t)listO[i]     * D_))[lane];
            float4 v1 = ((const float4*)(pb + (size_t)listO[i + 1] * D_))[lane];
            add4(o0, v0); add4(o1, v1);
        }
        if (i < cO) add4(o0, ((const float4*)(pb + (size_t)listO[i] * D_))[lane]);
        accO = o0; add4(accO, o1);
    }

    // ---- knowledge part: word_word * word_exist_matrix over 2048 cols ----
    {
        const float4* ww4 = (const float4*)(word_word + (size_t)bw * W_);
        const float4* we4 = (const float4*)(word_exist_matrix + (size_t)bw * W_);
        const int cbase = wid * 512;
        #pragma unroll
        for (int c4 = 0; c4 < 4; ++c4) {
            int vec = wid * 128 + c4 * 32 + lane;
            float4 m1 = ww4[vec], m2 = we4[vec];
            float mx = m1.x * m2.x, my = m1.y * m2.y, mz = m1.z * m2.z, mw = m1.w * m2.w;
            int col0 = cbase + c4 * 128 + lane * 4;
            unsigned bb;
            bb = __ballot_sync(0xffffffffu, mx != 0.f); if (mx != 0.f) listK[wid][cK + __popc(bb & lt)] = col0;     cK += __popc(bb);
            bb = __ballot_sync(0xffffffffu, my != 0.f); if (my != 0.f) listK[wid][cK + __popc(bb & lt)] = col0 + 1; cK += __popc(bb);
            bb = __ballot_sync(0xffffffffu, mz != 0.f); if (mz != 0.f) listK[wid][cK + __popc(bb & lt)] = col0 + 2; cK += __popc(bb);
            bb = __ballot_sync(0xffffffffu, mw != 0.f); if (mw != 0.f) listK[wid][cK + __popc(bb & lt)] = col0 + 3; cK += __popc(bb);
        }
        __syncwarp();
        float4 k0 = {0,0,0,0}, k1 = {0,0,0,0}, k2 = {0,0,0,0}, k3 = {0,0,0,0};
        int i = 0;
        for (; i + 4 <= cK; i += 4) {
            int j0 = listK[wid][i], j1 = listK[wid][i+1], j2 = listK[wid][i+2], j3 = listK[wid][i+3];
            float4 v0 = ((const float4*)(word_outputs + (((size_t)(j0 >> 9) * B_ + b) * L_ + (j0 & 511)) * D_))[lane];
            float4 v1 = ((const float4*)(word_outputs + (((size_t)(j1 >> 9) * B_ + b) * L_ + (j1 & 511)) * D_))[lane];
            float4 v2 = ((const float4*)(word_outputs + (((size_t)(j2 >> 9) * B_ + b) * L_ + (j2 & 511)) * D_))[lane];
            float4 v3 = ((const float4*)(word_outputs + (((size_t)(j3 >> 9) * B_ + b) * L_ + (j3 & 511)) * D_))[lane];
            add4(k0, v0); add4(k1, v1); add4(k2, v2); add4(k3, v3);
        }
        for (; i < cK; ++i) {
            int j0 = listK[wid][i];
            add4(k0, ((const float4*)(word_outputs + (((size_t)(j0 >> 9) * B_ + b) * L_ + (j0 & 511)) * D_))[lane]);
        }
        add4(k0, k1); add4(k2, k3); accK = k0; add4(accK, k2);
    }

    // ---- segment dependency part: 512 cols, same segment ----
    {
        const int s = w >> 9, l = w & 511;
        const float4* dp4 = (const float4*)(depend_relation + (((size_t)s * B_ + b) * L_ + l) * L_);
        const float* xb = word_outputs + ((size_t)s * B_ + b) * L_ * D_;
        float4 m = dp4[wid * 32 + lane];
        int col0 = wid * 128 + lane * 4;
        unsigned bb;
        bb = __ballot_sync(0xffffffffu, m.x != 0.f); if (m.x != 0.f) listS[wid][cS + __popc(bb & lt)] = col0;     cS += __popc(bb);
        bb = __ballot_sync(0xffffffffu, m.y != 0.f); if (m.y != 0.f) listS[wid][cS + __popc(bb & lt)] = col0 + 1; cS += __popc(bb);
        bb = __ballot_sync(0xffffffffu, m.z != 0.f); if (m.z != 0.f) listS[wid][cS + __popc(bb & lt)] = col0 + 2; cS += __popc(bb);
        bb = __ballot_sync(0xffffffffu, m.w != 0.f); if (m.w != 0.f) listS[wid][cS + __popc(bb & lt)] = col0 + 3; cS += __popc(bb);
        __syncwarp();
        float4 s0 = {0,0,0,0}, s1 = {0,0,0,0}, s2 = {0,0,0,0}, s3 = {0,0,0,0};
        int i = 0;
        for (; i + 4 <= cS; i += 4) {
            int j0 = listS[wid][i], j1 = listS[wid][i+1], j2 = listS[wid][i+2], j3 = listS[wid][i+3];
            float4 v0 = ((const float4*)(xb + (size_t)j0 * D_))[lane];
            float4 v1 = ((const float4*)(xb + (size_t)j1 * D_))[lane];
            float4 v2 = ((const float4*)(xb + (size_t)j2 * D_))[lane];
            float4 v3 = ((const float4*)(xb + (size_t)j3 * D_))[lane];
            add4(s0, v0); add4(s1, v1); add4(s2, v2); add4(s3, v3);
        }
        for (; i < cS; ++i)
            add4(s0, ((const float4*)(xb + (size_t)listS[wid][i] * D_))[lane]);
        add4(s0, s1); add4(s2, s3); accS = s0; add4(accS, s2);
    }

    // ---- cross-warp combine ----
    *(float4*)&comb[wid][0][4 * lane] = accO;
    *(float4*)&comb[wid][1][4 * lane] = accK;
    *(float4*)&comb[wid][2][4 * lane] = accS;
    if (lane == 0) { scn[wid][0] = cK; scn[wid][1] = cS; }
    __syncthreads();

    const int d = tid;
    float aO = comb[0][0][d] + comb[1][0][d] + comb[2][0][d] + comb[3][0][d];
    float aK = comb[0][1][d] + comb[1][1][d] + comb[2][1][d] + comb[3][1][d];
    float aS = comb[0][2][d] + comb[1][2][d] + comb[2][2][d] + comb[3][2][d];
    int tK = scn[0][0] + scn[1][0] + scn[2][0] + scn[3][0];
    int tS = scn[0][1] + scn[1][1] + scn[2][1] + scn[3][1];
    float invK = 1.f / ((float)tK + 1e-30f);
    float invS = 1.f / ((float)tS + 1e-30f);

    float* ag = g_agg + (size_t)bw * 384;
    ag[d]       = aO;               // H-space, bias included
    ag[128 + d] = aK * invK;
    ag[256 + d] = aS * invS;
    if (tid == 0) {
        g_coef[bw * 4 + 1] = (float)tK * invK;
        g_coef[bw * 4 + 2] = (float)tS * invS;
        int pos = atomicAdd(&g_n, 1);
        g_list[pos] = bw;
        atomicAdd(&g_bcnt[b], 1);
    }
}

// ---------------- kernel 3: warp-per-word update ----------------
// 384 blocks x 8 warps = 3072 warp slots; warp handles one word end-to-end
// (lane owns 4 output dims). No block barriers; warp-local smem broadcast
// with __syncwarp. p0 = passthrough (already projected), p1/p2 = GEMV.
__global__ void __launch_bounds__(256) k_update(
    const float* __restrict__ wk_W, const float* __restrict__ wk_b,
    const float* __restrict__ ws_W, const float* __restrict__ ws_b,
    const float* __restrict__ up_W, const float* __restrict__ up_b)
{
    const int tid = threadIdx.x;
    const int wid = tid >> 5, lane = tid & 31;
    const int d0 = lane * 4;
    __shared__ float sa[8][128];
    __shared__ float sh[8][128];
    const int N = g_n;
    const float4 bU = *(const float4*)(up_b + d0);

    for (int i = blockIdx.x * 8 + wid; i < N; i += gridDim.x * 8) {
        const int wd = g_list[i];
        const float* ag = g_agg + (size_t)wd * 384;
        float4 u = bU;

        #pragma unroll
        for (int p = 0; p < 3; ++p) {
            float4 h;
            if (p == 0) {
                h = *(const float4*)(ag + d0);
            } else {
                float4 a = *(const float4*)(ag + p * 128 + d0);
                *(float4*)&sa[wid][d0] = a;
                __syncwarp();
                const float* Wp = (p == 1) ? wk_W : ws_W;
                const float* bp = (p == 1) ? wk_b : ws_b;
                float cf = g_coef[wd * 4 + p];
                float4 bia = *(const float4*)(bp + d0);
                h = make_float4(cf * bia.x, cf * bia.y, cf * bia.z, cf * bia.w);
                #pragma unroll 4
                for (int s = 0; s < 128; ++s) {
                    float av = sa[wid][s];
                    float4 w = *(const float4*)(Wp + s * 128 + d0);
                    h.x = fmaf(av, w.x, h.x); h.y = fmaf(av, w.y, h.y);
                    h.z = fmaf(av, w.z, h.z); h.w = fmaf(av, w.w, h.w);
                }
            }
            // L2 normalize (warp-local)
            float ss = h.x * h.x + h.y * h.y + h.z * h.z + h.w * h.w;
            ss += __shfl_xor_sync(0xffffffffu, ss, 16);
            ss += __shfl_xor_sync(0xffffffffu, ss, 8);
            ss += __shfl_xor_sync(0xffffffffu, ss, 4);
            ss += __shfl_xor_sync(0xffffffffu, ss, 2);
            ss += __shfl_xor_sync(0xffffffffu, ss, 1);
            float inv = 1.f / (sqrtf(ss) + 1e-30f);
            h.x *= inv; h.y *= inv; h.z *= inv; h.w *= inv;
            *(float4*)&sh[wid][d0] = h;
            __syncwarp();
            // up-projection accumulate
            const float* Up = up_W + p * 16384;
            #pragma unroll 4
            for (int s = 0; s < 128; ++s) {
                float hv = sh[wid][s];
                float4 w = *(const float4*)(Up + s * 128 + d0);
                u.x = fmaf(hv, w.x, u.x); u.y = fmaf(hv, w.y, u.y);
                u.z = fmaf(hv, w.z, u.z); u.w = fmaf(hv, w.w, u.w);
            }
            __syncwarp();  // protect sa/sh reuse by next part
        }
        // relu + pooled accumulation
        const int b = wd >> 11;
        float* gp = g_goal + b * 128 + d0;
        atomicAdd(gp + 0, fmaxf(u.x, 0.f));
        atomicAdd(gp + 1, fmaxf(u.y, 0.f));
        atomicAdd(gp + 2, fmaxf(u.z, 0.f));
        atomicAdd(gp + 3, fmaxf(u.w, 0.f));
    }
}

// ---------------- kernel 4: gates + output (proven form) ----------------
__global__ void __launch_bounds__(1024) k_final(
    const float* __restrict__ node_hidden,
    const float* __restrict__ wg_W, const float* __restrict__ wg_b,
    const float* __restrict__ fg_W, const float* __restrict__ fg_b,
    float* __restrict__ out)
{
    const int b = blockIdx.x;
    const int tid = threadIdx.x;
    const int d = tid & 127, kq = tid >> 7;
    __shared__ float gws[128], nh[128];
    __shared__ float p1[8][128], p2[8][128];

    if (tid < 128) {
        float inv = 1.f / ((float)g_bcnt[b] + 1e-30f);
        gws[tid] = g_goal[b * 128 + tid] * inv;
        nh[tid] = node_hidden[b * 128 + tid];
    }
    __syncthreads();

    float s1 = 0.f, s2 = 0.f;
    #pragma unroll
    for (int kk = 0; kk < 16; ++kk) {
        int k = kq * 16 + kk;
        s1 = fmaf(gws[k], wg_W[k * 128 + d], s1);
    }
    #pragma unroll
    for (int kk = 0; kk < 32; ++kk) {
        int k = kq * 32 + kk;
        float x = (k < 128) ? gws[k] : nh[k - 128];
        s2 = fmaf(x, fg_W[k * 128 + d], s2);
    }
    p1[kq][d] = s1; p2[kq][d] = s2;
    __syncthreads();

    if (tid < 128) {
        float t1 = wg_b[tid], t2 = fg_b[tid];
        #pragma unroll
        for (int q = 0; q < 8; ++q) { t1 += p1[q][tid]; t2 += p2[q][tid]; }
        float gu = fmaxf(t1, 0.f);
        float f = 1.f / (1.f + expf(-t2));
        out[b * 128 + tid] = fmaxf(f, 0.1f) * nh[tid] + (1.f - f) * gu;
    }
}

// ---------------- launch ----------------
extern "C" void kernel_launch(void* const* d_in, const int* in_sizes, int n_in,
                              void* d_out, int out_size) {
    const float* word_outputs      = (const float*)d_in[0];
    const float* node_hidden       = (const float*)d_in[1];
    const float* op_embedding      = (const float*)d_in[2];
    const float* word_operator     = (const float*)d_in[3];
    const float* word_word         = (const float*)d_in[4];
    const float* depend_relation   = (const float*)d_in[5];
    const float* word_exist_matrix = (const float*)d_in[6];
    const float* word_exist_seq    = (const float*)d_in[7];
    const float* goal_word         = (const float*)d_in[8];
    const float* o_w_W = (const float*)d_in[9];
    const float* o_w_b = (const float*)d_in[10];
    const float* wk_W  = (const float*)d_in[11];
    const float* wk_b  = (const float*)d_in[12];
    const float* ws_W  = (const float*)d_in[13];
    const float* ws_b  = (const float*)d_in[14];
    const float* up_W  = (const float*)d_in[15];
    const float* up_b  = (const float*)d_in[16];
    const float* wg_W  = (const float*)d_in[17];
    const float* wg_b  = (const float*)d_in[18];
    const float* fg_W  = (const float*)d_in[19];
    const float* fg_b  = (const float*)d_in[20];
    float* out = (float*)d_out;

    k_prep<<<64, 256>>>(op_embedding, o_w_W, o_w_b);
    k_aggregate<<<dim3(W_, B_), 128>>>(word_outputs, word_operator, word_word,
                                       depend_relation, word_exist_matrix,
                                       word_exist_seq, goal_word);
    k_update<<<384, 256>>>(wk_W, wk_b, ws_W, ws_b, up_W, up_b);
    k_final<<<B_, 1024>>>(node_hidden, wg_W, wg_b, fg_W, fg_b, out);
}

// round 16
// speedup vs baseline: 1.3223x; 1.2834x over previous
#include <cuda_runtime.h>

#define S_   4
#define B_   8
#define L_   512
#define D_   128
#define NOP_ 64
#define W_   2048   // S_*L_

// ---------------- scratch (device globals; no allocation) ----------------
__device__ float g_agg[B_ * W_ * 3 * D_];   // per selected word: [h_o | a_k(normed) | a_s(normed)]
__device__ float g_coef[B_ * W_ * 4];       // [-, rowsumK, rowsumS]
__device__ float g_opproj[B_ * NOP_ * D_];  // op_embedding @ o_w_W + o_w_b
__device__ float g_goal[B_ * D_];           // pooled sum of relu(word_updated)
__device__ int   g_bcnt[B_];
__device__ int   g_list[B_ * W_];
__device__ int   g_n;

// ---------------- helpers ----------------
__device__ __forceinline__ void add4(float4& a, const float4 v) {
    a.x += v.x; a.y += v.y; a.z += v.z; a.w += v.w;
}
__device__ __forceinline__ void team_bar(int tg) {
    asm volatile("bar.sync %0, 64;" :: "r"(tg + 1) : "memory");
}

// ---------------- kernel 1: prep = reset + op projection (fast form) ----------------
// grid 64 x 256. Block computes 8 rows of proj[b,o,:] = emb@W + b.
// Thread owns 4 output cols of one row; emb rows staged in smem, weight
// reads coalesced LDG.128 shared across the block via L1.
__global__ void __launch_bounds__(256) k_prep(
    const float* __restrict__ op_embedding,
    const float* __restrict__ o_w_W, const float* __restrict__ o_w_b)
{
    const int tid = threadIdx.x;
    if (blockIdx.x == 0) {
        for (int t = tid; t < B_ * D_; t += 256) g_goal[t] = 0.f;
        if (tid < B_) g_bcnt[tid] = 0;
        if (tid == 0) g_n = 0;
    }

    const int r = tid >> 5;               // row within block
    const int c4 = (tid & 31) * 4;        // output col block
    const int row = blockIdx.x * 8 + r;   // 0..511 = b*64 + o
    __shared__ float es[8][128];

    *(float4*)&es[r][c4] = *(const float4*)(op_embedding + (size_t)row * D_ + c4);
    __syncthreads();

    float4 acc = *(const float4*)(o_w_b + c4);
    #pragma unroll 4
    for (int dd = 0; dd < 128; ++dd) {
        float e = es[r][dd];
        float4 w = *(const float4*)(o_w_W + dd * 128 + c4);
        acc.x = fmaf(e, w.x, acc.x); acc.y = fmaf(e, w.y, acc.y);
        acc.z = fmaf(e, w.z, acc.z); acc.w = fmaf(e, w.w, acc.w);
    }
    *(float4*)(g_opproj + (size_t)row * D_ + c4) = acc;
}

// ---------------- kernel 2: aggregate neighbors (proven R3 form, unchanged) ----------------
__global__ void __launch_bounds__(128) k_aggregate(
    const float* __restrict__ word_outputs,
    const float* __restrict__ word_operator,
    const float* __restrict__ word_word,
    const float* __restrict__ depend_relation,
    const float* __restrict__ word_exist_matrix,
    const float* __restrict__ word_exist_seq,
    const float* __restrict__ goal_word)
{
    const int w = blockIdx.x, b = blockIdx.y;
    const int bw = b * W_ + w;
    if (goal_word[bw] == 0.f || word_exist_seq[bw] == 0.f) return;

    const int tid = threadIdx.x;
    const int lane = tid & 31, wid = tid >> 5;
    const unsigned lt = (1u << lane) - 1u;

    __shared__ int   listK[4][512];
    __shared__ int   listS[4][128];
    __shared__ int   listO[64];
    __shared__ float comb[4][3][128];
    __shared__ int   scn[4][2];

    float4 accO = {0,0,0,0}, accK = {0,0,0,0}, accS = {0,0,0,0};
    int cK = 0, cS = 0;

    // ---- operator part: gather pre-projected rows (H-space), warp 0 only ----
    if (wid == 0) {
        const float4* wo4 = (const float4*)(word_operator + (size_t)bw * NOP_);
        float4 m = (lane < 16) ? wo4[lane] : make_float4(0.f,0.f,0.f,0.f);
        int col0 = lane * 4, cO = 0;
        unsigned bb;
        bb = __ballot_sync(0xffffffffu, m.x != 0.f); if (m.x != 0.f) listO[cO + __popc(bb & lt)] = col0;     cO += __popc(bb);
        bb = __ballot_sync(0xffffffffu, m.y != 0.f); if (m.y != 0.f) listO[cO + __popc(bb & lt)] = col0 + 1; cO += __popc(bb);
        bb = __ballot_sync(0xffffffffu, m.z != 0.f); if (m.z != 0.f) listO[cO + __popc(bb & lt)] = col0 + 2; cO += __popc(bb);
        bb = __ballot_sync(0xffffffffu, m.w != 0.f); if (m.w != 0.f) listO[cO + __popc(bb & lt)] = col0 + 3; cO += __popc(bb);
        __syncwarp();
        const float* pb = g_opproj + (size_t)b * NOP_ * D_;
        float4 o0 = {0,0,0,0}, o1 = {0,0,0,0};
        int i = 0;
        for (; i + 2 <= cO; i += 2) {
            float4 v0 = ((const float4*)(pb + (size_t)listO[i]     * D_))[lane];
            float4 v1 = ((const float4*)(pb + (size_t)listO[i + 1] * D_))[lane];
            add4(o0, v0); add4(o1, v1);
        }
        if (i < cO) add4(o0, ((const float4*)(pb + (size_t)listO[i] * D_))[lane]);
        accO = o0; add4(accO, o1);
    }

    // ---- knowledge part: word_word * word_exist_matrix over 2048 cols ----
    {
        const float4* ww4 = (const float4*)(word_word + (size_t)bw * W_);
        const float4* we4 = (const float4*)(word_exist_matrix + (size_t)bw * W_);
        const int cbase = wid * 512;
        #pragma unroll
        for (int c4 = 0; c4 < 4; ++c4) {
            int vec = wid * 128 + c4 * 32 + lane;
            float4 m1 = ww4[vec], m2 = we4[vec];
            float mx = m1.x * m2.x, my = m1.y * m2.y, mz = m1.z * m2.z, mw = m1.w * m2.w;
            int col0 = cbase + c4 * 128 + lane * 4;
            unsigned bb;
            bb = __ballot_sync(0xffffffffu, mx != 0.f); if (mx != 0.f) listK[wid][cK + __popc(bb & lt)] = col0;     cK += __popc(bb);
            bb = __ballot_sync(0xffffffffu, my != 0.f); if (my != 0.f) listK[wid][cK + __popc(bb & lt)] = col0 + 1; cK += __popc(bb);
            bb = __ballot_sync(0xffffffffu, mz != 0.f); if (mz != 0.f) listK[wid][cK + __popc(bb & lt)] = col0 + 2; cK += __popc(bb);
            bb = __ballot_sync(0xffffffffu, mw != 0.f); if (mw != 0.f) listK[wid][cK + __popc(bb & lt)] = col0 + 3; cK += __popc(bb);
        }
        __syncwarp();
        float4 k0 = {0,0,0,0}, k1 = {0,0,0,0}, k2 = {0,0,0,0}, k3 = {0,0,0,0};
        int i = 0;
        for (; i + 4 <= cK; i += 4) {
            int j0 = listK[wid][i], j1 = listK[wid][i+1], j2 = listK[wid][i+2], j3 = listK[wid][i+3];
            float4 v0 = ((const float4*)(word_outputs + (((size_t)(j0 >> 9) * B_ + b) * L_ + (j0 & 511)) * D_))[lane];
            float4 v1 = ((const float4*)(word_outputs + (((size_t)(j1 >> 9) * B_ + b) * L_ + (j1 & 511)) * D_))[lane];
            float4 v2 = ((const float4*)(word_outputs + (((size_t)(j2 >> 9) * B_ + b) * L_ + (j2 & 511)) * D_))[lane];
            float4 v3 = ((const float4*)(word_outputs + (((size_t)(j3 >> 9) * B_ + b) * L_ + (j3 & 511)) * D_))[lane];
            add4(k0, v0); add4(k1, v1); add4(k2, v2); add4(k3, v3);
        }
        for (; i < cK; ++i) {
            int j0 = listK[wid][i];
            add4(k0, ((const float4*)(word_outputs + (((size_t)(j0 >> 9) * B_ + b) * L_ + (j0 & 511)) * D_))[lane]);
        }
        add4(k0, k1); add4(k2, k3); accK = k0; add4(accK, k2);
    }

    // ---- segment dependency part: 512 cols, same segment ----
    {
        const int s = w >> 9, l = w & 511;
        const float4* dp4 = (const float4*)(depend_relation + (((size_t)s * B_ + b) * L_ + l) * L_);
        const float* xb = word_outputs + ((size_t)s * B_ + b) * L_ * D_;
        float4 m = dp4[wid * 32 + lane];
        int col0 = wid * 128 + lane * 4;
        unsigned bb;
        bb = __ballot_sync(0xffffffffu, m.x != 0.f); if (m.x != 0.f) listS[wid][cS + __popc(bb & lt)] = col0;     cS += __popc(bb);
        bb = __ballot_sync(0xffffffffu, m.y != 0.f); if (m.y != 0.f) listS[wid][cS + __popc(bb & lt)] = col0 + 1; cS += __popc(bb);
        bb = __ballot_sync(0xffffffffu, m.z != 0.f); if (m.z != 0.f) listS[wid][cS + __popc(bb & lt)] = col0 + 2; cS += __popc(bb);
        bb = __ballot_sync(0xffffffffu, m.w != 0.f); if (m.w != 0.f) listS[wid][cS + __popc(bb & lt)] = col0 + 3; cS += __popc(bb);
        __syncwarp();
        float4 s0 = {0,0,0,0}, s1 = {0,0,0,0}, s2 = {0,0,0,0}, s3 = {0,0,0,0};
        int i = 0;
        for (; i + 4 <= cS; i += 4) {
            int j0 = listS[wid][i], j1 = listS[wid][i+1], j2 = listS[wid][i+2], j3 = listS[wid][i+3];
            float4 v0 = ((const float4*)(xb + (size_t)j0 * D_))[lane];
            float4 v1 = ((const float4*)(xb + (size_t)j1 * D_))[lane];
            float4 v2 = ((const float4*)(xb + (size_t)j2 * D_))[lane];
            float4 v3 = ((const float4*)(xb + (size_t)j3 * D_))[lane];
            add4(s0, v0); add4(s1, v1); add4(s2, v2); add4(s3, v3);
        }
        for (; i < cS; ++i)
            add4(s0, ((const float4*)(xb + (size_t)listS[wid][i] * D_))[lane]);
        add4(s0, s1); add4(s2, s3); accS = s0; add4(accS, s2);
    }

    // ---- cross-warp combine ----
    *(float4*)&comb[wid][0][4 * lane] = accO;
    *(float4*)&comb[wid][1][4 * lane] = accK;
    *(float4*)&comb[wid][2][4 * lane] = accS;
    if (lane == 0) { scn[wid][0] = cK; scn[wid][1] = cS; }
    __syncthreads();

    const int d = tid;
    float aO = comb[0][0][d] + comb[1][0][d] + comb[2][0][d] + comb[3][0][d];
    float aK = comb[0][1][d] + comb[1][1][d] + comb[2][1][d] + comb[3][1][d];
    float aS = comb[0][2][d] + comb[1][2][d] + comb[2][2][d] + comb[3][2][d];
    int tK = scn[0][0] + scn[1][0] + scn[2][0] + scn[3][0];
    int tS = scn[0][1] + scn[1][1] + scn[2][1] + scn[3][1];
    float invK = 1.f / ((float)tK + 1e-30f);
    float invS = 1.f / ((float)tS + 1e-30f);

    float* ag = g_agg + (size_t)bw * 384;
    ag[d]       = aO;               // H-space, bias included
    ag[128 + d] = aK * invK;
    ag[256 + d] = aS * invS;
    if (tid == 0) {
        g_coef[bw * 4 + 1] = (float)tK * invK;
        g_coef[bw * 4 + 2] = (float)tS * invS;
        int pos = atomicAdd(&g_n, 1);
        g_list[pos] = bw;
        atomicAdd(&g_bcnt[b], 1);
    }
}

// ---------------- kernel 3: GEMVs + norm + up-proj (proven R3 team form) ----------------
// 2-warp teams; each team does 8 words, each warp 64 of 128 output dims.
// p0 = passthrough (pre-projected), p1/p2 = GEMV; weights amortized 8x.
__global__ void __launch_bounds__(256) k_update(
    const float* __restrict__ wk_W, const float* __restrict__ wk_b,
    const float* __restrict__ ws_W, const float* __restrict__ ws_b,
    const float* __restrict__ up_W, const float* __restrict__ up_b)
{
    const int tid = threadIdx.x;
    const int lane = tid & 31, wid = tid >> 5;
    const int half = wid & 1, tg = wid >> 1;
    const int t64 = tid & 63;
    const int team = blockIdx.x * 4 + tg;
    const int nteams = gridDim.x * 4;
    const int N = g_n;
    const int dim0 = half * 64 + lane * 2;

    __shared__ float as[4][8][128];
    __shared__ float hs[4][8][128];
    __shared__ float ssp[4][8][2];

    const float2 bU = *(const float2*)(up_b + dim0);

    for (int base = team * 8; base < N; base += nteams * 8) {
        int idx[8]; bool val[8];
        #pragma unroll
        for (int g = 0; g < 8; ++g) {
            val[g] = (base + g) < N;
            idx[g] = val[g] ? g_list[base + g] : 0;
        }
        float2 u[8];
        #pragma unroll
        for (int g = 0; g < 8; ++g) u[g] = bU;

        #pragma unroll
        for (int p = 0; p < 3; ++p) {
            // stage aggregates for this part
            #pragma unroll
            for (int r = 0; r < 4; ++r) {
                int q = r * 64 + t64;
                int g = q >> 5, off = (q & 31) * 4;
                float4 v = val[g] ? *(const float4*)(g_agg + (size_t)idx[g] * 384 + p * 128 + off)
                                  : make_float4(0.f,0.f,0.f,0.f);
                *(float4*)(&as[tg][g][off]) = v;
            }
            team_bar(tg);

            float2 h[8];
            if (p == 0) {
                #pragma unroll
                for (int g = 0; g < 8; ++g) h[g] = *(const float2*)(&as[tg][g][dim0]);
            } else {
                const float* Wp = (p == 1) ? wk_W : ws_W;
                const float* bp = (p == 1) ? wk_b : ws_b;
                const float2 bia = *(const float2*)(bp + dim0);
                #pragma unroll
                for (int g = 0; g < 8; ++g) {
                    float cf = val[g] ? g_coef[idx[g] * 4 + p] : 0.f;
                    h[g] = make_float2(cf * bia.x, cf * bia.y);
                }
                #pragma unroll 4
                for (int s4 = 0; s4 < 32; ++s4) {
                    float2 w0 = *(const float2*)(Wp + (s4 * 4 + 0) * 128 + dim0);
                    float2 w1 = *(const float2*)(Wp + (s4 * 4 + 1) * 128 + dim0);
                    float2 w2 = *(const float2*)(Wp + (s4 * 4 + 2) * 128 + dim0);
                    float2 w3 = *(const float2*)(Wp + (s4 * 4 + 3) * 128 + dim0);
                    #pragma unroll
                    for (int g = 0; g < 8; ++g) {
                        float4 av = *(const float4*)(&as[tg][g][s4 * 4]);
                        h[g].x = fmaf(av.x, w0.x, fmaf(av.y, w1.x, fmaf(av.z, w2.x, fmaf(av.w, w3.x, h[g].x))));
                        h[g].y = fmaf(av.x, w0.y, fmaf(av.y, w1.y, fmaf(av.z, w2.y, fmaf(av.w, w3.y, h[g].y))));
                    }
                }
            }
            // L2 norm across the team (warp half-reduction + smem exchange)
            #pragma unroll
            for (int g = 0; g < 8; ++g) {
                float ss = h[g].x * h[g].x + h[g].y * h[g].y;
                ss += __shfl_xor_sync(0xffffffffu, ss, 16);
                ss += __shfl_xor_sync(0xffffffffu, ss, 8);
                ss += __shfl_xor_sync(0xffffffffu, ss, 4);
                ss += __shfl_xor_sync(0xffffffffu, ss, 2);
                ss += __shfl_xor_sync(0xffffffffu, ss, 1);
                if (lane == 0) ssp[tg][g][half] = ss;
            }
            team_bar(tg);
            #pragma unroll
            for (int g = 0; g < 8; ++g) {
                float inv = 1.f / (sqrtf(ssp[tg][g][0] + ssp[tg][g][1]) + 1e-30f);
                *(float2*)(&hs[tg][g][dim0]) = make_float2(h[g].x * inv, h[g].y * inv);
            }
            team_bar(tg);
            // up-projection accumulate for this part
            const float* Up = up_W + (size_t)p * 128 * 128;
            #pragma unroll 4
            for (int s4 = 0; s4 < 32; ++s4) {
                float2 w0 = *(const float2*)(Up + (s4 * 4 + 0) * 128 + dim0);
                float2 w1 = *(const float2*)(Up + (s4 * 4 + 1) * 128 + dim0);
                float2 w2 = *(const float2*)(Up + (s4 * 4 + 2) * 128 + dim0);
                float2 w3 = *(const float2*)(Up + (s4 * 4 + 3) * 128 + dim0);
                #pragma unroll
                for (int g = 0; g < 8; ++g) {
                    float4 hv = *(const float4*)(&hs[tg][g][s4 * 4]);
                    u[g].x = fmaf(hv.x, w0.x, fmaf(hv.y, w1.x, fmaf(hv.z, w2.x, fmaf(hv.w, w3.x, u[g].x))));
                    u[g].y = fmaf(hv.x, w0.y, fmaf(hv.y, w1.y, fmaf(hv.z, w2.y, fmaf(hv.w, w3.y, u[g].y))));
                }
            }
            team_bar(tg);  // protect as/hs reuse in next part
        }
        // relu + pooled accumulation
        #pragma unroll
        for (int g = 0; g < 8; ++g) {
            if (val[g]) {
                int b = idx[g] >> 11;
                atomicAdd(g_goal + b * 128 + dim0,     fmaxf(u[g].x, 0.f));
                atomicAdd(g_goal + b * 128 + dim0 + 1, fmaxf(u[g].y, 0.f));
            }
        }
    }
}

// ---------------- kernel 4: gates + output (proven form) ----------------
__global__ void __launch_bounds__(1024) k_final(
    const float* __restrict__ node_hidden,
    const float* __restrict__ wg_W, const float* __restrict__ wg_b,
    const float* __restrict__ fg_W, const float* __restrict__ fg_b,
    float* __restrict__ out)
{
    const int b = blockIdx.x;
    const int tid = threadIdx.x;
    const int d = tid & 127, kq = tid >> 7;
    __shared__ float gws[128], nh[128];
    __shared__ float p1[8][128], p2[8][128];

    if (tid < 128) {
        float inv = 1.f / ((float)g_bcnt[b] + 1e-30f);
        gws[tid] = g_goal[b * 128 + tid] * inv;
        nh[tid] = node_hidden[b * 128 + tid];
    }
    __syncthreads();

    float s1 = 0.f, s2 = 0.f;
    #pragma unroll
    for (int kk = 0; kk < 16; ++kk) {
        int k = kq * 16 + kk;
        s1 = fmaf(gws[k], wg_W[k * 128 + d], s1);
    }
    #pragma unroll
    for (int kk = 0; kk < 32; ++kk) {
        int k = kq * 32 + kk;
        float x = (k < 128) ? gws[k] : nh[k - 128];
        s2 = fmaf(x, fg_W[k * 128 + d], s2);
    }
    p1[kq][d] = s1; p2[kq][d] = s2;
    __syncthreads();

    if (tid < 128) {
        float t1 = wg_b[tid], t2 = fg_b[tid];
        #pragma unroll
        for (int q = 0; q < 8; ++q) { t1 += p1[q][tid]; t2 += p2[q][tid]; }
        float gu = fmaxf(t1, 0.f);
        float f = 1.f / (1.f + expf(-t2));
        out[b * 128 + tid] = fmaxf(f, 0.1f) * nh[tid] + (1.f - f) * gu;
    }
}

// ---------------- launch ----------------
extern "C" void kernel_launch(void* const* d_in, const int* in_sizes, int n_in,
                              void* d_out, int out_size) {
    const float* word_outputs      = (const float*)d_in[0];
    const float* node_hidden       = (const float*)d_in[1];
    const float* op_embedding      = (const float*)d_in[2];
    const float* word_operator     = (const float*)d_in[3];
    const float* word_word         = (const float*)d_in[4];
    const float* depend_relation   = (const float*)d_in[5];
    const float* word_exist_matrix = (const float*)d_in[6];
    const float* word_exist_seq    = (const float*)d_in[7];
    const float* goal_word         = (const float*)d_in[8];
    const float* o_w_W = (const float*)d_in[9];
    const float* o_w_b = (const float*)d_in[10];
    const float* wk_W  = (const float*)d_in[11];
    const float* wk_b  = (const float*)d_in[12];
    const float* ws_W  = (const float*)d_in[13];
    const float* ws_b  = (const float*)d_in[14];
    const float* up_W  = (const float*)d_in[15];
    const float* up_b  = (const float*)d_in[16];
    const float* wg_W  = (const float*)d_in[17];
    const float* wg_b  = (const float*)d_in[18];
    const float* fg_W  = (const float*)d_in[19];
    const float* fg_b  = (const float*)d_in[20];
    float* out = (float*)d_out;

    k_prep<<<64, 256>>>(op_embedding, o_w_W, o_w_b);
    k_aggregate<<<dim3(W_, B_), 128>>>(word_outputs, word_operator, word_word,
                                       depend_relation, word_exist_matrix,
                                       word_exist_seq, goal_word);
    k_update<<<148, 256>>>(wk_W, wk_b, ws_W, ws_b, up_W, up_b);
    k_final<<<B_, 1024>>>(node_hidden, wg_W, wg_b, fg_W, fg_b, out);
}